// round 8
// baseline (speedup 1.0000x reference)
#include <cuda_runtime.h>
#include <cuda_fp16.h>
#include <cstdint>
#include <math.h>

#define C_CELLS 128
#define H_DIM   256
#define CE_DIM  64
#define MAXG    2048
#define KB      16

// ---------------- device scratch ----------------
__device__ float  g_part[KB * C_CELLS * H_DIM];
__device__ __half g_Ah[C_CELLS * H_DIM];                // A fp16, [c/2][h][c&1]
__device__ float  g_Bbuf[MAXG * H_DIM];
__device__ __align__(16) __half g_w2t[H_DIM * H_DIM];   // fp16 W2a^T [n][k]
__device__ __align__(16) __half g_w2bt[H_DIM * H_DIM];  // fp16 (W2b^T)/128 [n][k]

__device__ __forceinline__ float eluf(float x) {
    return x > 0.f ? x : (__expf(x) - 1.f);
}
__device__ __forceinline__ uint32_t smem_to_u32(const void* p) {
    uint32_t a;
    asm("{ .reg .u64 t; cvta.to.shared.u64 t, %1; cvt.u32.u64 %0, t; }" : "=r"(a) : "l"(p));
    return a;
}
__device__ __forceinline__ void ldsm4(uint32_t* r, uint32_t addr) {
    asm volatile("ldmatrix.sync.aligned.m8n8.x4.shared.b16 {%0,%1,%2,%3}, [%4];"
                 : "=r"(r[0]), "=r"(r[1]), "=r"(r[2]), "=r"(r[3]) : "r"(addr));
}
__device__ __forceinline__ void ldsm4t(uint32_t* r, uint32_t addr) {
    asm volatile("ldmatrix.sync.aligned.m8n8.x4.trans.shared.b16 {%0,%1,%2,%3}, [%4];"
                 : "=r"(r[0]), "=r"(r[1]), "=r"(r[2]), "=r"(r[3]) : "r"(addr));
}
__device__ __forceinline__ void mma16816(float* c, const uint32_t* a, const uint32_t* b) {
    asm volatile("mma.sync.aligned.m16n8k16.row.col.f32.f16.f16.f32 "
                 "{%0,%1,%2,%3}, {%4,%5,%6,%7}, {%8,%9}, {%0,%1,%2,%3};"
                 : "+f"(c[0]), "+f"(c[1]), "+f"(c[2]), "+f"(c[3])
                 : "r"(a[0]), "r"(a[1]), "r"(a[2]), "r"(a[3]), "r"(b[0]), "r"(b[1]));
}
__device__ __forceinline__ void sts32h2(uint32_t addr, __half2 v) {
    uint32_t u = *reinterpret_cast<uint32_t*>(&v);
    asm volatile("st.shared.u32 [%0], %1;" :: "r"(addr), "r"(u) : "memory");
}
__device__ __forceinline__ __half2 h2ex2(__half2 x) {
    uint32_t xi = *reinterpret_cast<uint32_t*>(&x), ri;
    asm("ex2.approx.f16x2 %0, %1;" : "=r"(ri) : "r"(xi));
    return *reinterpret_cast<__half2*>(&ri);
}

#define SWZ512(b) ((b) ^ (((b) >> 5) & 0x70))

// ---------------- SMEM layout ----------------
#define SM_W2T   0          // 131072
#define SM_BUF   131072     // h1 transposed [256 h][128 c]*2B = 65536
#define SM_CTRLH 196608     // 128 halves (256 B)
#define SM_PART  196864     // 512 f32 (2048 B)
#define SM_R     198912     // 256 f32
#define SM_W3A   199936     // 256 f32
#define SM_LOG4  200960     // 4 x 128 f32 (2048 B)
#define SM_RED   203008     // 32 f32
#define SM_TOTAL 203136

// ---------------------------------------------------------------------------
__global__ void k_prepA(const float* __restrict__ ctrl, const float* __restrict__ w,
                        int G, int kc) {
    extern __shared__ float sc[];
    const int kb = blockIdx.x, cb = blockIdx.y, t = threadIdx.x;
    const int k0 = kb * kc;
    int kn = G - k0; if (kn > kc) kn = kc; if (kn < 0) kn = 0;
    for (int i = t; i < 8 * kn; i += 256) {
        int ci = i / kn, k = i - ci * kn;
        sc[ci * kc + k] = ctrl[(cb * 8 + ci) * G + k0 + k];
    }
    __syncthreads();
    float acc[8] = {0.f,0.f,0.f,0.f,0.f,0.f,0.f,0.f};
    int k = 0;
    for (; k + 1 < kn; k += 2) {
        const float w0 = w[(k0 + k) * H_DIM + t];
        const float w1 = w[(k0 + k + 1) * H_DIM + t];
        #pragma unroll
        for (int ci = 0; ci < 8; ci++) {
            const float2 cv = *(const float2*)&sc[ci * kc + k];
            acc[ci] = fmaf(cv.x, w0, acc[ci]);
            acc[ci] = fmaf(cv.y, w1, acc[ci]);
        }
    }
    if (k < kn) {
        const float w0 = w[(k0 + k) * H_DIM + t];
        #pragma unroll
        for (int ci = 0; ci < 8; ci++) acc[ci] = fmaf(sc[ci * kc + k], w0, acc[ci]);
    }
    #pragma unroll
    for (int ci = 0; ci < 8; ci++)
        g_part[(kb * C_CELLS + cb * 8 + ci) * H_DIM + t] = acc[ci];
}

__global__ void k_prepB(const float* __restrict__ b1,
                        const float* __restrict__ ce_w2, const float* __restrict__ ce_b2,
                        const float* __restrict__ gw1) {
    __shared__ float s_hid[H_DIM];
    __shared__ float s_ce[CE_DIM];
    const int c = blockIdx.x, t = threadIdx.x;
    float a = b1[t];
    #pragma unroll
    for (int kb = 0; kb < KB; kb++) a += g_part[(kb * C_CELLS + c) * H_DIM + t];
    s_hid[t] = eluf(a);
    __syncthreads();
    if (t < CE_DIM) {
        float v = ce_b2[t];
        #pragma unroll 4
        for (int kk = 0; kk < H_DIM; kk++) v = fmaf(s_hid[kk], ce_w2[kk * CE_DIM + t], v);
        s_ce[t] = v;
    }
    __syncthreads();
    float av = 0.f;
    #pragma unroll
    for (int j = 0; j < CE_DIM; j++) av = fmaf(s_ce[j], gw1[(1 + j) * H_DIM + t], av);
    g_Ah[(c >> 1) * (2 * H_DIM) + t * 2 + (c & 1)] = __float2half(av);
}

__global__ void k_prep2(const float* __restrict__ gene_table, const float* __restrict__ shift_vec,
                        const int* __restrict__ gidx, const float* __restrict__ gw1,
                        const float* __restrict__ gb1, const float* __restrict__ gw2, int G) {
    const int t = threadIdx.x;
    if ((int)blockIdx.x < G) {
        __shared__ float s_ge[CE_DIM];
        __shared__ float s_shift;
        const int g = blockIdx.x;
        const int gi = gidx[g];
        if (t < CE_DIM) s_ge[t] = gene_table[gi * CE_DIM + t];
        if (t == 0) s_shift = shift_vec[gi];
        __syncthreads();
        float a = gb1[t] + s_shift * gw1[129 * H_DIM + t] + (float)C_CELLS * gw1[130 * H_DIM + t];
        #pragma unroll
        for (int j = 0; j < CE_DIM; j++) a = fmaf(s_ge[j], gw1[(65 + j) * H_DIM + t], a);
        g_Bbuf[g * H_DIM + t] = a;
    } else {
        const int n = blockIdx.x - G;
        g_w2t[n * H_DIM + t]  = __float2half(gw2[t * H_DIM + n]);
        g_w2bt[n * H_DIM + t] = __float2half(gw2[(256 + t) * H_DIM + n] * (1.f / (float)C_CELLS));
    }
}

// ---------------------------------------------------------------------------
__global__ void __launch_bounds__(512, 1)
k_main(const float* __restrict__ ctrl, const int* __restrict__ gidx,
       const float* __restrict__ gw1, const float* __restrict__ gb2,
       const float* __restrict__ gw3,
       float* __restrict__ out, int G, int Gc) {
    extern __shared__ char smem[];
    const uint32_t smem_u = smem_to_u32(smem);
    const int t = threadIdx.x;
    const int lane = t & 31, w = t >> 5;

    __half2* s_ctrlh2 = (__half2*)(smem + SM_CTRLH);
    __half*  s_ctrlh  = (__half*)(smem + SM_CTRLH);
    float* s_part = (float*)(smem + SM_PART);
    float* s_r    = (float*)(smem + SM_R);
    float* s_w3a  = (float*)(smem + SM_W3A);
    float* s_log4 = (float*)(smem + SM_LOG4);
    float* s_red  = (float*)(smem + SM_RED);

    // ---- one-time init ----
    {
        const uint4* src = (const uint4*)g_w2t;
        for (int idx = t; idx < 8192; idx += 512) {
            int n = idx >> 5, kq = idx & 31;
            uint32_t local = (uint32_t)n * 512u + (uint32_t)kq * 16u;
            *(uint4*)(smem + SM_W2T + SWZ512(local)) = src[idx];
        }
        if (t < 256) s_w3a[t] = gw3[t];
    }

    // ---- pass1 constants ----
    const int h = t & 255, mhalf = t >> 8;
    const int rot = (h >> 3) & 3;
    const __half2 w102 = __float2half2_rn(gw1[h]);
    const __half2 L2E2 = __float2half2_rn(1.44269504f);
    const __half2 HNEG1 = __float2half2_rn(-1.f);
    const __half2 HZERO = __float2half2_rn(0.f);
    const uint32_t xm = (uint32_t)(h & 7) << 4;
    const uint32_t rowbase = smem_u + SM_BUF + (uint32_t)h * 256u;

    __half2 aReg[32];
    {
        const __half2* Ap = (const __half2*)g_Ah;
        #pragma unroll
        for (int q = 0; q < 32; q++) {
            int cp = mhalf * 32 + ((q + rot) & 31);
            aReg[q] = Ap[(uint32_t)cp * 256u + h];
        }
    }

    // GEMM constants
    const int mrow = (w & 3) * 32, nb = (w >> 2) * 64;
    const int krl = (lane & 7) + ((lane >> 4) << 3);
    const uint32_t xmA = (uint32_t)(krl & 7) << 4;
    const uint32_t mcoff = (uint32_t)(mrow + (((lane >> 3) & 1) << 3)) * 2u;
    const uint32_t aBase0 = smem_u + SM_BUF + (uint32_t)krl * 256u + (mcoff ^ xmA);
    const uint32_t aBase1 = smem_u + SM_BUF + (uint32_t)krl * 256u + ((mcoff + 32u) ^ xmA);
    const uint32_t b_rb = (uint32_t)(nb + ((lane >> 4) << 3) + (lane & 7)) * 512u
                        + (uint32_t)(((lane >> 3) & 1) * 16);

    // r assignment: col rcol, k-half rkh; W2b^T fp16 (pre-scaled by 1/128)
    const int  rcol  = w * 16 + (lane >> 1);
    const int  rkh   = lane & 1;
    const float rbias = (rkh == 0) ? gb2[rcol] : 0.f;
    const __half* wbase = g_w2bt + (uint32_t)rcol * 256u + (uint32_t)rkh * 128u;
    const float* pbase = s_part + rkh * 128;        // + 0 / +256 halves

    // ---- gene-0 state + prefetch ----
    float bcur = 0.f, cpref = 0.f;
    {
        const int g0 = blockIdx.x;
        const int gi0 = gidx[g0];
        bcur = g_Bbuf[g0 * H_DIM + h];
        if (t < 128) cpref = ctrl[t * Gc + gi0];
    }
    __syncthreads();

    for (int g = blockIdx.x; g < G; g += gridDim.x) {
        if (t < 128) s_ctrlh[t] = __float2half(cpref);
        __syncthreads();                                        // S1

        const int gn = g + gridDim.x;
        const bool hasnext = gn < G;
        int gi_next = 0;
        if (hasnext) gi_next = gidx[gn];

        // ---- pass1: h1 fp16x2 -> BUF (transposed) + partial sums ----
        {
            const __half2 brow2 = __float2half2_rn(bcur);
            __half2 av[4] = {HZERO, HZERO, HZERO, HZERO};
            #pragma unroll
            for (int q = 0; q < 32; q++) {
                const int qi = (q + rot) & 31;
                __half2 c2 = s_ctrlh2[mhalf * 32 + qi];
                __half2 z2 = __hfma2(c2, w102, __hadd2(aReg[q], brow2));
                __half2 e2 = h2ex2(__hmul2(z2, L2E2));
                __half2 v2 = __hadd2(__hmax2(z2, HZERO),
                                     __hmin2(__hadd2(e2, HNEG1), HZERO));
                av[q & 3] = __hadd2(av[q & 3], v2);
                sts32h2(rowbase + (((uint32_t)(mhalf * 128 + qi * 4)) ^ xm), v2);
            }
            float2 f0 = __half22float2(av[0]), f1 = __half22float2(av[1]);
            float2 f2 = __half22float2(av[2]), f3 = __half22float2(av[3]);
            s_part[mhalf * 256 + h] = ((f0.x + f0.y) + (f1.x + f1.y))
                                    + ((f2.x + f2.y) + (f3.x + f3.y));
        }
        __syncthreads();                                        // S2

        // prefetch next gene (hidden under GEMM)
        float bnext = 0.f;
        if (hasnext) {
            bnext = g_Bbuf[gn * H_DIM + h];
            if (t < 128) cpref = ctrl[t * Gc + gi_next];
        }

        // ---- GEMM (16 k-steps) with vectorized r interleaved ----
        float acc[2][8][4];
        #pragma unroll
        for (int mh = 0; mh < 2; mh++)
            #pragma unroll
            for (int j = 0; j < 8; j++)
                #pragma unroll
                for (int q = 0; q < 4; q++) acc[mh][j][q] = 0.f;

        float racc = rbias;
        #pragma unroll
        for (int ks = 0; ks < 16; ks++) {
            const uint32_t ao = (uint32_t)ks * 4096u;
            uint32_t a0r[4], a1r[4];
            ldsm4t(a0r, aBase0 + ao);
            ldsm4t(a1r, aBase1 + ao);
            const uint32_t bk = b_rb + (uint32_t)ks * 32u;
            #pragma unroll
            for (int j2 = 0; j2 < 4; j2++) {
                uint32_t b[4];
                ldsm4(b, smem_u + SM_W2T + SWZ512(bk + (uint32_t)j2 * (16u * 512u)));
                mma16816(acc[0][j2 * 2],     a0r, b);
                mma16816(acc[0][j2 * 2 + 1], a0r, b + 2);
                mma16816(acc[1][j2 * 2],     a1r, b);
                mma16816(acc[1][j2 * 2 + 1], a1r, b + 2);
            }
            // r: one LDG.128 of fp16 weights + LDS.128 part reads (broadcast)
            {
                const uint4 raw = *(const uint4*)(wbase + ks * 8);
                const __half2* wh = (const __half2*)&raw;
                const float4 pl0 = *(const float4*)(pbase + ks * 8);
                const float4 pl1 = *(const float4*)(pbase + ks * 8 + 4);
                const float4 ph0 = *(const float4*)(pbase + 256 + ks * 8);
                const float4 ph1 = *(const float4*)(pbase + 256 + ks * 8 + 4);
                const float2 w0 = __half22float2(wh[0]);
                const float2 w1 = __half22float2(wh[1]);
                const float2 w2 = __half22float2(wh[2]);
                const float2 w3 = __half22float2(wh[3]);
                racc = fmaf(pl0.x + ph0.x, w0.x, racc);
                racc = fmaf(pl0.y + ph0.y, w0.y, racc);
                racc = fmaf(pl0.z + ph0.z, w1.x, racc);
                racc = fmaf(pl0.w + ph0.w, w1.y, racc);
                racc = fmaf(pl1.x + ph1.x, w2.x, racc);
                racc = fmaf(pl1.y + ph1.y, w2.y, racc);
                racc = fmaf(pl1.z + ph1.z, w3.x, racc);
                racc = fmaf(pl1.w + ph1.w, w3.y, racc);
            }
        }
        racc += __shfl_xor_sync(0xffffffffu, racc, 1);
        if (rkh == 0) s_r[rcol] = racc;
        __syncthreads();                                        // S3

        // ---- epilogue: per-ngroup logit arrays (no atomics) ----
        {
            float p[4] = {0.f, 0.f, 0.f, 0.f};
            const int nc = nb + ((lane & 3) << 1);
            #pragma unroll
            for (int mh = 0; mh < 2; mh++)
                #pragma unroll
                for (int j = 0; j < 8; j++) {
                    const int n0 = nc + j * 8;
                    const float w30 = s_w3a[n0], w31 = s_w3a[n0 + 1];
                    const float rr0 = s_r[n0],  rr1 = s_r[n0 + 1];
                    p[mh*2+0] = fmaf(eluf(acc[mh][j][0] + rr0), w30, p[mh*2+0]);
                    p[mh*2+0] = fmaf(eluf(acc[mh][j][1] + rr1), w31, p[mh*2+0]);
                    p[mh*2+1] = fmaf(eluf(acc[mh][j][2] + rr0), w30, p[mh*2+1]);
                    p[mh*2+1] = fmaf(eluf(acc[mh][j][3] + rr1), w31, p[mh*2+1]);
                }
            #pragma unroll
            for (int i = 0; i < 4; i++) {
                p[i] += __shfl_xor_sync(0xffffffffu, p[i], 1);
                p[i] += __shfl_xor_sync(0xffffffffu, p[i], 2);
            }
            if ((lane & 3) == 0) {
                const int ng = w >> 2;
                #pragma unroll
                for (int i = 0; i < 4; i++)
                    s_log4[ng * 128 + mrow + (i >> 1) * 16 + (i & 1) * 8 + (lane >> 2)] = p[i];
            }
        }
        __syncthreads();                                        // S4

        // ---- softmax (no max-subtraction; logits are tiny) ----
        {
            float e = 0.f;
            if (t < 128) {
                const float l = (s_log4[t] + s_log4[128 + t])
                              + (s_log4[256 + t] + s_log4[384 + t]);
                e = __expf(l);
            }
            float s = e;
            #pragma unroll
            for (int off = 16; off; off >>= 1) s += __shfl_xor_sync(0xffffffffu, s, off);
            if (t < 128 && lane == 0) s_red[w] = s;
            __syncthreads();                                    // S5
            if (t < 128) {
                const float tot = (s_red[0] + s_red[1]) + (s_red[2] + s_red[3]);
                out[t * G + g] = e / tot;
            }
        }
        bcur = bnext;
    }
}

// ---------------------------------------------------------------------------
extern "C" void kernel_launch(void* const* d_in, const int* in_sizes, int n_in,
                              void* d_out, int out_size) {
    const float* ctrl       = (const float*)d_in[0];
    const float* shift_vec  = (const float*)d_in[1];
    const int*   gidx       = (const int*)  d_in[2];
    const float* ce_w1      = (const float*)d_in[3];
    const float* ce_b1      = (const float*)d_in[4];
    const float* ce_w2      = (const float*)d_in[5];
    const float* ce_b2      = (const float*)d_in[6];
    const float* gene_table = (const float*)d_in[7];
    const float* g_w1       = (const float*)d_in[8];
    const float* g_b1       = (const float*)d_in[9];
    const float* g_w2       = (const float*)d_in[10];
    const float* g_b2       = (const float*)d_in[11];
    const float* g_w3       = (const float*)d_in[12];
    float* out = (float*)d_out;

    const int G  = in_sizes[2];
    const int Gc = in_sizes[0] / C_CELLS;
    int kc = (Gc + KB - 1) / KB;
    kc = (kc + 1) & ~1;

    int nsm = 148;
    cudaDeviceGetAttribute(&nsm, cudaDevAttrMultiProcessorCount, 0);
    if (nsm <= 0) nsm = 148;
    int grid = nsm < G ? nsm : G;

    cudaFuncSetAttribute(k_main, cudaFuncAttributeMaxDynamicSharedMemorySize, SM_TOTAL);
    cudaFuncSetAttribute(k_prepA, cudaFuncAttributeMaxDynamicSharedMemorySize,
                         8 * kc * (int)sizeof(float));

    k_prepA<<<dim3(KB, 16), 256, 8 * kc * sizeof(float)>>>(ctrl, ce_w1, Gc, kc);
    k_prepB<<<C_CELLS, H_DIM>>>(ce_b1, ce_w2, ce_b2, g_w1);
    k_prep2<<<G + H_DIM, H_DIM>>>(gene_table, shift_vec, gidx, g_w1, g_b1, g_w2, G);
    k_main<<<grid, 512, SM_TOTAL>>>(ctrl, gidx, g_w1, g_b2, g_w3, out, G, Gc);
}